// round 1
// baseline (speedup 1.0000x reference)
#include <cuda_runtime.h>
#include <math.h>

#define EMBED 1024
#define NHEAD 16
#define HDIM  64
#define MLPH  4096
#define BATCH 2
#define SEQ   2048
#define NTOK  4096   // BATCH*SEQ
#define BH    32     // BATCH*NHEAD

// ---------------- scratch (static device globals; no allocation) ----------------
__device__ float g_h  [(size_t)NTOK * EMBED];   // ln1 / ln2 output
__device__ float g_q  [(size_t)NTOK * EMBED];   // [B,H,S,Dh]
__device__ float g_k  [(size_t)NTOK * EMBED];
__device__ float g_v  [(size_t)NTOK * EMBED];
__device__ float g_att[(size_t)NTOK * EMBED];   // attention out in [B,S,D]
__device__ float g_x1 [(size_t)NTOK * EMBED];   // x + proj(attn)
__device__ float g_mlp[(size_t)NTOK * MLPH];    // gelu(fc1)
__device__ float g_sc [(size_t)BH * SEQ * SEQ]; // score matrices (536 MB)

// ---------------- reductions ----------------
__device__ __forceinline__ float warpSum(float v) {
    #pragma unroll
    for (int o = 16; o; o >>= 1) v += __shfl_xor_sync(0xffffffffu, v, o);
    return v;
}
__device__ __forceinline__ float warpMax(float v) {
    #pragma unroll
    for (int o = 16; o; o >>= 1) v = fmaxf(v, __shfl_xor_sync(0xffffffffu, v, o));
    return v;
}

// ---------------- LayerNorm: one block per row of 1024 ----------------
__global__ __launch_bounds__(256) void ln_kernel(
    const float* __restrict__ x, const float* __restrict__ g,
    const float* __restrict__ b, float* __restrict__ o)
{
    size_t row = blockIdx.x;
    int tid = threadIdx.x;
    const float4* xr = reinterpret_cast<const float4*>(x + row * EMBED);
    float4 v = xr[tid];
    float s  = v.x + v.y + v.z + v.w;
    float ss = v.x*v.x + v.y*v.y + v.z*v.z + v.w*v.w;
    __shared__ float rs_[8], rss_[8];
    s = warpSum(s); ss = warpSum(ss);
    int w = tid >> 5, l = tid & 31;
    if (l == 0) { rs_[w] = s; rss_[w] = ss; }
    __syncthreads();
    float tot = 0.f, tot2 = 0.f;
    #pragma unroll
    for (int i = 0; i < 8; i++) { tot += rs_[i]; tot2 += rss_[i]; }
    float mu  = tot * (1.0f / EMBED);
    float var = tot2 * (1.0f / EMBED) - mu * mu;
    float rstd = rsqrtf(var + 1e-5f);
    float4 gg = reinterpret_cast<const float4*>(g)[tid];
    float4 bb = reinterpret_cast<const float4*>(b)[tid];
    float4 r;
    r.x = (v.x - mu) * rstd * gg.x + bb.x;
    r.y = (v.y - mu) * rstd * gg.y + bb.y;
    r.z = (v.z - mu) * rstd * gg.z + bb.z;
    r.w = (v.w - mu) * rstd * gg.w + bb.w;
    reinterpret_cast<float4*>(o + row * EMBED)[tid] = r;
}

// ---------------- Softmax over rows of length 2048 ----------------
__global__ __launch_bounds__(256) void softmax_kernel(float* __restrict__ p)
{
    size_t row = blockIdx.x;
    int tid = threadIdx.x;
    float4* pr = reinterpret_cast<float4*>(p + row * (size_t)SEQ);
    float4 a = pr[tid], b = pr[tid + 256];
    float m = fmaxf(fmaxf(fmaxf(a.x, a.y), fmaxf(a.z, a.w)),
                    fmaxf(fmaxf(b.x, b.y), fmaxf(b.z, b.w)));
    __shared__ float red[8];
    m = warpMax(m);
    int w = tid >> 5, l = tid & 31;
    if (l == 0) red[w] = m;
    __syncthreads();
    float mm = red[0];
    #pragma unroll
    for (int i = 1; i < 8; i++) mm = fmaxf(mm, red[i]);
    a.x = __expf(a.x - mm); a.y = __expf(a.y - mm);
    a.z = __expf(a.z - mm); a.w = __expf(a.w - mm);
    b.x = __expf(b.x - mm); b.y = __expf(b.y - mm);
    b.z = __expf(b.z - mm); b.w = __expf(b.w - mm);
    float s = a.x + a.y + a.z + a.w + b.x + b.y + b.z + b.w;
    __syncthreads();             // before reusing red[]
    s = warpSum(s);
    if (l == 0) red[w] = s;
    __syncthreads();
    float tot = 0.f;
    #pragma unroll
    for (int i = 0; i < 8; i++) tot += red[i];
    float inv = 1.0f / tot;
    a.x *= inv; a.y *= inv; a.z *= inv; a.w *= inv;
    b.x *= inv; b.y *= inv; b.z *= inv; b.w *= inv;
    pr[tid] = a; pr[tid + 256] = b;
}

// ---------------- Tiled SIMT GEMM with templated epilogues ----------------
enum { EPI_QKV = 0, EPI_SCORES = 1, EPI_PV = 2, EPI_BR = 3, EPI_GELU = 4 };

template<int BN, int TN, bool TB, int EPI>
__global__ __launch_bounds__(256, 2) void gemm_kernel(
    const float* __restrict__ A, const float* __restrict__ B,
    const float* __restrict__ bias, const float* __restrict__ res,
    float* __restrict__ C, int M, int N, int K)
{
    constexpr int BM = 128, BK = 16, TM = 8;
    constexpr int NTX = BN / TN;
    __shared__ float As[BK][BM];
    __shared__ float Bs[BK][BN];

    const int tid = threadIdx.x;
    const int m0 = blockIdx.y * BM;
    const int n0 = blockIdx.x * BN;
    const int bz = blockIdx.z;
    const float* Ap = A + (size_t)bz * (size_t)M * K;
    const float* Bp = B + (size_t)bz * (size_t)K * N;

    // A tile load mapping (transpose-store): rows ar, ar+64; 4 floats at ac
    const int ar = tid >> 2;
    const int ac = (tid & 3) << 2;
    // B tile load mapping
    int br, bc;
    if (TB)            { br = tid >> 2; bc = (tid & 3) << 2; }
    else if (BN == 128){ br = tid >> 5; bc = (tid & 31) << 2; }
    else               { br = tid >> 4; bc = (tid & 15) << 2; }

    const int tx = tid % NTX;
    const int ty = tid / NTX;

    float acc[TM][TN];
    #pragma unroll
    for (int i = 0; i < TM; i++)
        #pragma unroll
        for (int j = 0; j < TN; j++) acc[i][j] = 0.f;

    float4 pa0, pa1, pb0, pb1;
    // prefetch first tile
    pa0 = *reinterpret_cast<const float4*>(Ap + (size_t)(m0 + ar) * K + ac);
    pa1 = *reinterpret_cast<const float4*>(Ap + (size_t)(m0 + ar + 64) * K + ac);
    if constexpr (TB) {
        pb0 = *reinterpret_cast<const float4*>(Bp + (size_t)(n0 + br) * K + bc);
        pb1 = *reinterpret_cast<const float4*>(Bp + (size_t)(n0 + br + 64) * K + bc);
    } else if constexpr (BN == 128) {
        pb0 = *reinterpret_cast<const float4*>(Bp + (size_t)br * N + n0 + bc);
        pb1 = *reinterpret_cast<const float4*>(Bp + (size_t)(br + 8) * N + n0 + bc);
    } else {
        pb0 = *reinterpret_cast<const float4*>(Bp + (size_t)br * N + n0 + bc);
    }

    for (int kt = 0; kt < K; kt += BK) {
        // commit prefetched tile to smem
        As[ac + 0][ar] = pa0.x; As[ac + 1][ar] = pa0.y;
        As[ac + 2][ar] = pa0.z; As[ac + 3][ar] = pa0.w;
        As[ac + 0][ar + 64] = pa1.x; As[ac + 1][ar + 64] = pa1.y;
        As[ac + 2][ar + 64] = pa1.z; As[ac + 3][ar + 64] = pa1.w;
        if constexpr (TB) {
            Bs[bc + 0][br] = pb0.x; Bs[bc + 1][br] = pb0.y;
            Bs[bc + 2][br] = pb0.z; Bs[bc + 3][br] = pb0.w;
            Bs[bc + 0][br + 64] = pb1.x; Bs[bc + 1][br + 64] = pb1.y;
            Bs[bc + 2][br + 64] = pb1.z; Bs[bc + 3][br + 64] = pb1.w;
        } else if constexpr (BN == 128) {
            *reinterpret_cast<float4*>(&Bs[br][bc]) = pb0;
            *reinterpret_cast<float4*>(&Bs[br + 8][bc]) = pb1;
        } else {
            *reinterpret_cast<float4*>(&Bs[br][bc]) = pb0;
        }
        __syncthreads();

        int ktn = kt + BK;
        if (ktn < K) {
            pa0 = *reinterpret_cast<const float4*>(Ap + (size_t)(m0 + ar) * K + ktn + ac);
            pa1 = *reinterpret_cast<const float4*>(Ap + (size_t)(m0 + ar + 64) * K + ktn + ac);
            if constexpr (TB) {
                pb0 = *reinterpret_cast<const float4*>(Bp + (size_t)(n0 + br) * K + ktn + bc);
                pb1 = *reinterpret_cast<const float4*>(Bp + (size_t)(n0 + br + 64) * K + ktn + bc);
            } else if constexpr (BN == 128) {
                pb0 = *reinterpret_cast<const float4*>(Bp + (size_t)(ktn + br) * N + n0 + bc);
                pb1 = *reinterpret_cast<const float4*>(Bp + (size_t)(ktn + br + 8) * N + n0 + bc);
            } else {
                pb0 = *reinterpret_cast<const float4*>(Bp + (size_t)(ktn + br) * N + n0 + bc);
            }
        }

        #pragma unroll
        for (int kk = 0; kk < BK; kk++) {
            float a[TM], b[TN];
            *reinterpret_cast<float4*>(&a[0]) = *reinterpret_cast<const float4*>(&As[kk][ty * TM]);
            *reinterpret_cast<float4*>(&a[4]) = *reinterpret_cast<const float4*>(&As[kk][ty * TM + 4]);
            *reinterpret_cast<float4*>(&b[0]) = *reinterpret_cast<const float4*>(&Bs[kk][tx * TN]);
            if constexpr (TN == 8)
                *reinterpret_cast<float4*>(&b[4]) = *reinterpret_cast<const float4*>(&Bs[kk][tx * TN + 4]);
            #pragma unroll
            for (int i = 0; i < TM; i++)
                #pragma unroll
                for (int j = 0; j < TN; j++)
                    acc[i][j] += a[i] * b[j];
        }
        __syncthreads();
    }

    const int row0 = m0 + ty * TM;
    const int col0 = n0 + tx * TN;

    if constexpr (EPI == EPI_QKV) {
        #pragma unroll
        for (int i = 0; i < TM; i++) {
            int n = row0 + i;
            int bb2 = n >> 11, s2 = n & 2047;
            #pragma unroll
            for (int j = 0; j < TN; j++) {
                int c = col0 + j;
                int part = c >> 10, rr = c & 1023;
                int hh = rr >> 6, dd = rr & 63;
                size_t idx = ((size_t)(bb2 * NHEAD + hh) * SEQ + s2) * HDIM + dd;
                float val = acc[i][j];
                if (part == 0)      g_q[idx] = val;
                else if (part == 1) g_k[idx] = val;
                else                g_v[idx] = val;
            }
        }
    } else if constexpr (EPI == EPI_SCORES) {
        float* Cp = C + (size_t)bz * (size_t)M * N;
        #pragma unroll
        for (int i = 0; i < TM; i++)
            #pragma unroll
            for (int j = 0; j < TN; j++)
                Cp[(size_t)(row0 + i) * N + col0 + j] = acc[i][j] * 0.125f;
    } else if constexpr (EPI == EPI_PV) {
        int bb2 = bz >> 4, hh = bz & 15;
        #pragma unroll
        for (int i = 0; i < TM; i++)
            #pragma unroll
            for (int j = 0; j < TN; j++)
                g_att[((size_t)(bb2 * SEQ + row0 + i)) * EMBED + hh * HDIM + col0 + j] = acc[i][j];
    } else if constexpr (EPI == EPI_BR) {
        #pragma unroll
        for (int i = 0; i < TM; i++)
            #pragma unroll
            for (int j = 0; j < TN; j++) {
                int r = row0 + i, c = col0 + j;
                size_t idx = (size_t)r * N + c;
                C[idx] = acc[i][j] + bias[c] + res[idx];
            }
    } else { // EPI_GELU
        #pragma unroll
        for (int i = 0; i < TM; i++)
            #pragma unroll
            for (int j = 0; j < TN; j++) {
                int r = row0 + i, c = col0 + j;
                float v2 = acc[i][j] + bias[c];
                C[(size_t)r * N + c] = 0.5f * v2 * (1.0f + erff(v2 * 0.70710678118654752f));
            }
    }
}

// ---------------- host launcher ----------------
extern "C" void kernel_launch(void* const* d_in, const int* in_sizes, int n_in,
                              void* d_out, int out_size)
{
    const float* x      = (const float*)d_in[0];
    const float* w_qkv  = (const float*)d_in[1];
    const float* w_proj = (const float*)d_in[2];
    const float* b_proj = (const float*)d_in[3];
    const float* w_fc1  = (const float*)d_in[4];
    const float* b_fc1  = (const float*)d_in[5];
    const float* w_fc2  = (const float*)d_in[6];
    const float* b_fc2  = (const float*)d_in[7];
    const float* g1     = (const float*)d_in[8];
    const float* be1    = (const float*)d_in[9];
    const float* g2     = (const float*)d_in[10];
    const float* be2    = (const float*)d_in[11];
    float* out = (float*)d_out;

    float *hbuf, *qb, *kb, *vb, *ab, *x1b, *mlpb, *scb;
    cudaGetSymbolAddress((void**)&hbuf, g_h);
    cudaGetSymbolAddress((void**)&qb,   g_q);
    cudaGetSymbolAddress((void**)&kb,   g_k);
    cudaGetSymbolAddress((void**)&vb,   g_v);
    cudaGetSymbolAddress((void**)&ab,   g_att);
    cudaGetSymbolAddress((void**)&x1b,  g_x1);
    cudaGetSymbolAddress((void**)&mlpb, g_mlp);
    cudaGetSymbolAddress((void**)&scb,  g_sc);

    // 1. ln1
    ln_kernel<<<NTOK, 256>>>(x, g1, be1, hbuf);
    // 2. qkv = h @ w_qkv  (scatter to q/k/v head-major)
    gemm_kernel<128, 8, false, EPI_QKV><<<dim3(3 * EMBED / 128, NTOK / 128, 1), 256>>>(
        hbuf, w_qkv, nullptr, nullptr, nullptr, NTOK, 3 * EMBED, EMBED);
    // 3. scores = Q @ K^T * scale   (batched over B*H)
    gemm_kernel<128, 8, true, EPI_SCORES><<<dim3(SEQ / 128, SEQ / 128, BH), 256>>>(
        qb, kb, nullptr, nullptr, scb, SEQ, SEQ, HDIM);
    // 4. softmax rows
    softmax_kernel<<<BH * SEQ, 256>>>(scb);
    // 5. attn_out = P @ V  (scatter back to [B,S,D])
    gemm_kernel<64, 4, false, EPI_PV><<<dim3(1, SEQ / 128, BH), 256>>>(
        scb, vb, nullptr, nullptr, nullptr, SEQ, HDIM, SEQ);
    // 6. x1 = x + attn_out @ w_proj + b_proj
    gemm_kernel<128, 8, false, EPI_BR><<<dim3(EMBED / 128, NTOK / 128, 1), 256>>>(
        ab, w_proj, b_proj, x, x1b, NTOK, EMBED, EMBED);
    // 7. ln2
    ln_kernel<<<NTOK, 256>>>(x1b, g2, be2, hbuf);
    // 8. mlp = gelu(h2 @ w_fc1 + b_fc1)
    gemm_kernel<128, 8, false, EPI_GELU><<<dim3(MLPH / 128, NTOK / 128, 1), 256>>>(
        hbuf, w_fc1, b_fc1, nullptr, mlpb, NTOK, MLPH, EMBED);
    // 9. out = x1 + mlp @ w_fc2 + b_fc2
    gemm_kernel<128, 8, false, EPI_BR><<<dim3(EMBED / 128, NTOK / 128, 1), 256>>>(
        mlpb, w_fc2, b_fc2, x1b, out, NTOK, EMBED, MLPH);
}

// round 2
// speedup vs baseline: 1.9322x; 1.9322x over previous
#include <cuda_runtime.h>
#include <cuda_bf16.h>
#include <math.h>
#include <stdint.h>

#define EMBED 1024
#define NHEAD 16
#define HDIM  64
#define MLPH  4096
#define BATCH 2
#define SEQ   2048
#define NTOK  4096   // BATCH*SEQ
#define BH    32     // BATCH*NHEAD

using bf16 = __nv_bfloat16;

// ---------------- scratch (static device globals; no allocation) ----------------
__device__ __align__(16) bf16 g_hhi [(size_t)NTOK * EMBED];
__device__ __align__(16) bf16 g_hlo [(size_t)NTOK * EMBED];
__device__ __align__(16) bf16 g_wqkvT_hi[(size_t)3 * EMBED * EMBED];
__device__ __align__(16) bf16 g_wqkvT_lo[(size_t)3 * EMBED * EMBED];
__device__ __align__(16) bf16 g_wprojT_hi[(size_t)EMBED * EMBED];
__device__ __align__(16) bf16 g_wprojT_lo[(size_t)EMBED * EMBED];
__device__ __align__(16) bf16 g_wfc1T_hi[(size_t)EMBED * MLPH];
__device__ __align__(16) bf16 g_wfc1T_lo[(size_t)EMBED * MLPH];
__device__ __align__(16) bf16 g_wfc2T_hi[(size_t)MLPH * EMBED];
__device__ __align__(16) bf16 g_wfc2T_lo[(size_t)MLPH * EMBED];
__device__ __align__(16) bf16 g_qhi [(size_t)NTOK * EMBED];   // [BH][S][Dh]
__device__ __align__(16) bf16 g_qlo [(size_t)NTOK * EMBED];
__device__ __align__(16) bf16 g_khi [(size_t)NTOK * EMBED];
__device__ __align__(16) bf16 g_klo [(size_t)NTOK * EMBED];
__device__ __align__(16) bf16 g_vThi[(size_t)NTOK * EMBED];   // [BH][Dh][S]
__device__ __align__(16) bf16 g_vTlo[(size_t)NTOK * EMBED];
__device__ __align__(16) float g_sc [(size_t)BH * SEQ * SEQ]; // fp32 scores
__device__ __align__(16) bf16 g_phi [(size_t)BH * SEQ * SEQ]; // softmax hi
__device__ __align__(16) bf16 g_plo [(size_t)BH * SEQ * SEQ]; // softmax lo
__device__ __align__(16) bf16 g_atthi[(size_t)NTOK * EMBED];  // [B*S][D]
__device__ __align__(16) bf16 g_attlo[(size_t)NTOK * EMBED];
__device__ __align__(16) float g_x1 [(size_t)NTOK * EMBED];
__device__ __align__(16) bf16 g_mlphi[(size_t)NTOK * MLPH];
__device__ __align__(16) bf16 g_mlplo[(size_t)NTOK * MLPH];

// ---------------- helpers ----------------
__device__ __forceinline__ float warpSum(float v) {
    #pragma unroll
    for (int o = 16; o; o >>= 1) v += __shfl_xor_sync(0xffffffffu, v, o);
    return v;
}
__device__ __forceinline__ float warpMax(float v) {
    #pragma unroll
    for (int o = 16; o; o >>= 1) v = fmaxf(v, __shfl_xor_sync(0xffffffffu, v, o));
    return v;
}
__device__ __forceinline__ void store_hilo2(bf16* __restrict__ Hi, bf16* __restrict__ Lo,
                                            size_t idx, float a, float b) {
    bf16 h0 = __float2bfloat16(a), h1 = __float2bfloat16(b);
    bf16 l0 = __float2bfloat16(a - __bfloat162float(h0));
    bf16 l1 = __float2bfloat16(b - __bfloat162float(h1));
    *(__nv_bfloat162*)(Hi + idx) = __halves2bfloat162(h0, h1);
    *(__nv_bfloat162*)(Lo + idx) = __halves2bfloat162(l0, l1);
}
__device__ __forceinline__ void store_hilo1(bf16* __restrict__ Hi, bf16* __restrict__ Lo,
                                            size_t idx, float a) {
    bf16 h = __float2bfloat16(a);
    Hi[idx] = h;
    Lo[idx] = __float2bfloat16(a - __bfloat162float(h));
}
__device__ __forceinline__ void mma16816(float* d, const uint32_t* a, const uint32_t* b) {
    asm volatile(
        "mma.sync.aligned.m16n8k16.row.col.f32.bf16.bf16.f32 "
        "{%0,%1,%2,%3},{%4,%5,%6,%7},{%8,%9},{%0,%1,%2,%3};\n"
        : "+f"(d[0]), "+f"(d[1]), "+f"(d[2]), "+f"(d[3])
        : "r"(a[0]), "r"(a[1]), "r"(a[2]), "r"(a[3]), "r"(b[0]), "r"(b[1]));
}

// ---------------- weight transpose + hi/lo split: W[K][N] -> T[N][K] ----------------
__global__ __launch_bounds__(256) void convT_kernel(
    const float* __restrict__ W, bf16* __restrict__ Thi, bf16* __restrict__ Tlo,
    int K, int N)
{
    __shared__ float t[32][33];
    int n0 = blockIdx.x * 32, k0 = blockIdx.y * 32;
    int tx = threadIdx.x & 31, ty0 = threadIdx.x >> 5;
    #pragma unroll
    for (int r = ty0; r < 32; r += 8)
        t[r][tx] = W[(size_t)(k0 + r) * N + n0 + tx];
    __syncthreads();
    #pragma unroll
    for (int r = ty0; r < 32; r += 8) {
        float v = t[tx][r];                 // = W[k0+tx][n0+r]
        size_t idx = (size_t)(n0 + r) * K + k0 + tx;
        bf16 h = __float2bfloat16(v);
        Thi[idx] = h;
        Tlo[idx] = __float2bfloat16(v - __bfloat162float(h));
    }
}

// ---------------- LayerNorm: fp32 in -> bf16 hi/lo out ----------------
__global__ __launch_bounds__(256) void ln_kernel(
    const float* __restrict__ x, const float* __restrict__ g,
    const float* __restrict__ b, bf16* __restrict__ Ohi, bf16* __restrict__ Olo)
{
    size_t row = blockIdx.x;
    int tid = threadIdx.x;
    const float4* xr = reinterpret_cast<const float4*>(x + row * EMBED);
    float4 v = xr[tid];
    float s  = v.x + v.y + v.z + v.w;
    float ss = v.x*v.x + v.y*v.y + v.z*v.z + v.w*v.w;
    __shared__ float rs_[8], rss_[8];
    s = warpSum(s); ss = warpSum(ss);
    int w = tid >> 5, l = tid & 31;
    if (l == 0) { rs_[w] = s; rss_[w] = ss; }
    __syncthreads();
    float tot = 0.f, tot2 = 0.f;
    #pragma unroll
    for (int i = 0; i < 8; i++) { tot += rs_[i]; tot2 += rss_[i]; }
    float mu  = tot * (1.0f / EMBED);
    float var = tot2 * (1.0f / EMBED) - mu * mu;
    float rstd = rsqrtf(var + 1e-5f);
    float4 gg = reinterpret_cast<const float4*>(g)[tid];
    float4 bb = reinterpret_cast<const float4*>(b)[tid];
    float r0 = (v.x - mu) * rstd * gg.x + bb.x;
    float r1 = (v.y - mu) * rstd * gg.y + bb.y;
    float r2 = (v.z - mu) * rstd * gg.z + bb.z;
    float r3 = (v.w - mu) * rstd * gg.w + bb.w;
    size_t base = row * EMBED + (size_t)tid * 4;
    store_hilo2(Ohi, Olo, base,     r0, r1);
    store_hilo2(Ohi, Olo, base + 2, r2, r3);
}

// ---------------- Softmax: fp32 scores -> bf16 hi/lo probs ----------------
__global__ __launch_bounds__(256) void softmax_kernel(
    const float* __restrict__ p, bf16* __restrict__ Phi, bf16* __restrict__ Plo)
{
    size_t row = blockIdx.x;
    int tid = threadIdx.x;
    const float4* pr = reinterpret_cast<const float4*>(p + row * (size_t)SEQ);
    float4 a = pr[tid], b = pr[tid + 256];
    float m = fmaxf(fmaxf(fmaxf(a.x, a.y), fmaxf(a.z, a.w)),
                    fmaxf(fmaxf(b.x, b.y), fmaxf(b.z, b.w)));
    __shared__ float red[8];
    m = warpMax(m);
    int w = tid >> 5, l = tid & 31;
    if (l == 0) red[w] = m;
    __syncthreads();
    float mm = red[0];
    #pragma unroll
    for (int i = 1; i < 8; i++) mm = fmaxf(mm, red[i]);
    a.x = __expf(a.x - mm); a.y = __expf(a.y - mm);
    a.z = __expf(a.z - mm); a.w = __expf(a.w - mm);
    b.x = __expf(b.x - mm); b.y = __expf(b.y - mm);
    b.z = __expf(b.z - mm); b.w = __expf(b.w - mm);
    float s = a.x + a.y + a.z + a.w + b.x + b.y + b.z + b.w;
    __syncthreads();
    s = warpSum(s);
    if (l == 0) red[w] = s;
    __syncthreads();
    float tot = 0.f;
    #pragma unroll
    for (int i = 0; i < 8; i++) tot += red[i];
    float inv = 1.0f / tot;
    size_t b0 = row * (size_t)SEQ + (size_t)tid * 4;
    size_t b1 = row * (size_t)SEQ + (size_t)(tid + 256) * 4;
    store_hilo2(Phi, Plo, b0,     a.x * inv, a.y * inv);
    store_hilo2(Phi, Plo, b0 + 2, a.z * inv, a.w * inv);
    store_hilo2(Phi, Plo, b1,     b.x * inv, b.y * inv);
    store_hilo2(Phi, Plo, b1 + 2, b.z * inv, b.w * inv);
}

// ---------------- 3-pass split-bf16 tensor-core GEMM ----------------
// A: [M][K] hi/lo bf16, B: [N][K] hi/lo bf16, fp32 accumulate.
enum { EPI_QKV = 0, EPI_SCORES = 1, EPI_PV = 2, EPI_BR = 3, EPI_GELU = 4 };

template<int BN, int NT, int EPI>
__global__ __launch_bounds__(NT) void mma_gemm(
    const bf16* __restrict__ Ahi, const bf16* __restrict__ Alo,
    const bf16* __restrict__ Bhi, const bf16* __restrict__ Blo,
    const float* __restrict__ bias, const float* __restrict__ res,
    float* __restrict__ Cf, bf16* __restrict__ Chi, bf16* __restrict__ Clo,
    int M, int N, int K, size_t sA, size_t sB)
{
    constexpr int BM = 128, BK = 32;
    constexpr int WN = BN / 32;             // warps along n
    constexpr int A_IT = (BM * 4) / NT;     // uint4 loads per thread per A matrix
    constexpr int B_IT = (BN * 4) / NT;
    constexpr int LDS_ = 40;                // padded smem row stride (bf16)

    __shared__ __align__(16) bf16 Ash[BM * LDS_];
    __shared__ __align__(16) bf16 Asl[BM * LDS_];
    __shared__ __align__(16) bf16 Bsh[BN * LDS_];
    __shared__ __align__(16) bf16 Bsl[BN * LDS_];

    const int tid = threadIdx.x;
    const int wid = tid >> 5, lane = tid & 31;
    const int g = lane >> 2, c4 = lane & 3;
    const int wm = wid / WN, wn = wid % WN;
    const int m0 = blockIdx.y * BM, n0 = blockIdx.x * BN;
    const int bz = blockIdx.z;

    const bf16* pAh = Ahi + (size_t)bz * sA;
    const bf16* pAl = Alo + (size_t)bz * sA;
    const bf16* pBh = Bhi + (size_t)bz * sB;
    const bf16* pBl = Blo + (size_t)bz * sB;

    float acc[4][4][4];
    #pragma unroll
    for (int i = 0; i < 4; i++)
        #pragma unroll
        for (int j = 0; j < 4; j++)
            #pragma unroll
            for (int k = 0; k < 4; k++) acc[i][j][k] = 0.f;

    uint4 rAh[A_IT], rAl[A_IT], rBh[B_IT], rBl[B_IT];

    // prefetch first chunk
    #pragma unroll
    for (int i = 0; i < A_IT; i++) {
        int idx = tid + i * NT; int row = idx >> 2; int ch = (idx & 3) << 3;
        size_t off = (size_t)(m0 + row) * K + ch;
        rAh[i] = *(const uint4*)(pAh + off);
        rAl[i] = *(const uint4*)(pAl + off);
    }
    #pragma unroll
    for (int i = 0; i < B_IT; i++) {
        int idx = tid + i * NT; int row = idx >> 2; int ch = (idx & 3) << 3;
        size_t off = (size_t)(n0 + row) * K + ch;
        rBh[i] = *(const uint4*)(pBh + off);
        rBl[i] = *(const uint4*)(pBl + off);
    }

    for (int kt = 0; kt < K; kt += BK) {
        // commit prefetched chunk
        #pragma unroll
        for (int i = 0; i < A_IT; i++) {
            int idx = tid + i * NT; int row = idx >> 2; int ch = (idx & 3) << 3;
            *(uint4*)&Ash[row * LDS_ + ch] = rAh[i];
            *(uint4*)&Asl[row * LDS_ + ch] = rAl[i];
        }
        #pragma unroll
        for (int i = 0; i < B_IT; i++) {
            int idx = tid + i * NT; int row = idx >> 2; int ch = (idx & 3) << 3;
            *(uint4*)&Bsh[row * LDS_ + ch] = rBh[i];
            *(uint4*)&Bsl[row * LDS_ + ch] = rBl[i];
        }
        __syncthreads();

        if (kt + BK < K) {
            #pragma unroll
            for (int i = 0; i < A_IT; i++) {
                int idx = tid + i * NT; int row = idx >> 2; int ch = (idx & 3) << 3;
                size_t off = (size_t)(m0 + row) * K + kt + BK + ch;
                rAh[i] = *(const uint4*)(pAh + off);
                rAl[i] = *(const uint4*)(pAl + off);
            }
            #pragma unroll
            for (int i = 0; i < B_IT; i++) {
                int idx = tid + i * NT; int row = idx >> 2; int ch = (idx & 3) << 3;
                size_t off = (size_t)(n0 + row) * K + kt + BK + ch;
                rBh[i] = *(const uint4*)(pBh + off);
                rBl[i] = *(const uint4*)(pBl + off);
            }
        }

        #pragma unroll
        for (int ks = 0; ks < 2; ks++) {
            const int kb = ks * 16 + 2 * c4;
            uint32_t ah[4][4], al[4][4], bh[4][2], bl[4][2];
            #pragma unroll
            for (int mf = 0; mf < 4; mf++) {
                int r = wm * 64 + mf * 16 + g;
                ah[mf][0] = *(const uint32_t*)&Ash[r * LDS_ + kb];
                ah[mf][1] = *(const uint32_t*)&Ash[(r + 8) * LDS_ + kb];
                ah[mf][2] = *(const uint32_t*)&Ash[r * LDS_ + kb + 8];
                ah[mf][3] = *(const uint32_t*)&Ash[(r + 8) * LDS_ + kb + 8];
                al[mf][0] = *(const uint32_t*)&Asl[r * LDS_ + kb];
                al[mf][1] = *(const uint32_t*)&Asl[(r + 8) * LDS_ + kb];
                al[mf][2] = *(const uint32_t*)&Asl[r * LDS_ + kb + 8];
                al[mf][3] = *(const uint32_t*)&Asl[(r + 8) * LDS_ + kb + 8];
            }
            #pragma unroll
            for (int nf = 0; nf < 4; nf++) {
                int nn = wn * 32 + nf * 8 + g;
                bh[nf][0] = *(const uint32_t*)&Bsh[nn * LDS_ + kb];
                bh[nf][1] = *(const uint32_t*)&Bsh[nn * LDS_ + kb + 8];
                bl[nf][0] = *(const uint32_t*)&Bsl[nn * LDS_ + kb];
                bl[nf][1] = *(const uint32_t*)&Bsl[nn * LDS_ + kb + 8];
            }
            #pragma unroll
            for (int mf = 0; mf < 4; mf++)
                #pragma unroll
                for (int nf = 0; nf < 4; nf++) {
                    mma16816(acc[mf][nf], ah[mf], bh[nf]);
                    mma16816(acc[mf][nf], ah[mf], bl[nf]);
                    mma16816(acc[mf][nf], al[mf], bh[nf]);
                }
        }
        __syncthreads();
    }

    // ---------------- epilogue ----------------
    #pragma unroll
    for (int mf = 0; mf < 4; mf++) {
        int r0 = m0 + wm * 64 + mf * 16 + g;
        #pragma unroll
        for (int nf = 0; nf < 4; nf++) {
            int cc = n0 + wn * 32 + nf * 8 + 2 * c4;
            float d0 = acc[mf][nf][0], d1 = acc[mf][nf][1];
            float d2 = acc[mf][nf][2], d3 = acc[mf][nf][3];

            if constexpr (EPI == EPI_SCORES) {
                float* out = Cf + (size_t)bz * ((size_t)M * N);
                *(float2*)&out[(size_t)r0 * N + cc]       = make_float2(d0 * 0.125f, d1 * 0.125f);
                *(float2*)&out[(size_t)(r0 + 8) * N + cc] = make_float2(d2 * 0.125f, d3 * 0.125f);
            } else if constexpr (EPI == EPI_BR) {
                float b0 = bias[cc], b1 = bias[cc + 1];
                size_t i0 = (size_t)r0 * N + cc, i1 = (size_t)(r0 + 8) * N + cc;
                *(float2*)&Cf[i0] = make_float2(d0 + b0 + res[i0], d1 + b1 + res[i0 + 1]);
                *(float2*)&Cf[i1] = make_float2(d2 + b0 + res[i1], d3 + b1 + res[i1 + 1]);
            } else if constexpr (EPI == EPI_GELU) {
                float b0 = bias[cc], b1 = bias[cc + 1];
                float v0 = d0 + b0, v1 = d1 + b1, v2 = d2 + b0, v3 = d3 + b1;
                v0 = 0.5f * v0 * (1.0f + erff(v0 * 0.70710678118654752f));
                v1 = 0.5f * v1 * (1.0f + erff(v1 * 0.70710678118654752f));
                v2 = 0.5f * v2 * (1.0f + erff(v2 * 0.70710678118654752f));
                v3 = 0.5f * v3 * (1.0f + erff(v3 * 0.70710678118654752f));
                store_hilo2(Chi, Clo, (size_t)r0 * N + cc, v0, v1);
                store_hilo2(Chi, Clo, (size_t)(r0 + 8) * N + cc, v2, v3);
            } else if constexpr (EPI == EPI_PV) {
                int bb = bz >> 4, hd = bz & 15;
                size_t i0 = ((size_t)(bb * SEQ + r0)) * EMBED + hd * HDIM + cc;
                size_t i1 = ((size_t)(bb * SEQ + r0 + 8)) * EMBED + hd * HDIM + cc;
                store_hilo2(g_atthi, g_attlo, i0, d0, d1);
                store_hilo2(g_atthi, g_attlo, i1, d2, d3);
            } else { // EPI_QKV
                int part = cc >> 10, rem = cc & 1023, hd = rem >> 6, dd = rem & 63;
                #pragma unroll
                for (int rr = 0; rr < 2; rr++) {
                    int r = r0 + rr * 8;
                    float e0 = rr ? d2 : d0, e1 = rr ? d3 : d1;
                    int bb = r >> 11, s = r & 2047;
                    size_t bh_ = (size_t)(bb * NHEAD + hd);
                    if (part == 0) {
                        store_hilo2(g_qhi, g_qlo, (bh_ * SEQ + s) * HDIM + dd, e0, e1);
                    } else if (part == 1) {
                        store_hilo2(g_khi, g_klo, (bh_ * SEQ + s) * HDIM + dd, e0, e1);
                    } else {
                        size_t vb = (bh_ * HDIM + dd) * SEQ + s;
                        store_hilo1(g_vThi, g_vTlo, vb, e0);
                        store_hilo1(g_vThi, g_vTlo, vb + SEQ, e1);
                    }
                }
            }
        }
    }
}

// ---------------- host launcher ----------------
extern "C" void kernel_launch(void* const* d_in, const int* in_sizes, int n_in,
                              void* d_out, int out_size)
{
    const float* x      = (const float*)d_in[0];
    const float* w_qkv  = (const float*)d_in[1];
    const float* w_proj = (const float*)d_in[2];
    const float* b_proj = (const float*)d_in[3];
    const float* w_fc1  = (const float*)d_in[4];
    const float* b_fc1  = (const float*)d_in[5];
    const float* w_fc2  = (const float*)d_in[6];
    const float* b_fc2  = (const float*)d_in[7];
    const float* g1     = (const float*)d_in[8];
    const float* be1    = (const float*)d_in[9];
    const float* g2     = (const float*)d_in[10];
    const float* be2    = (const float*)d_in[11];
    float* out = (float*)d_out;

    bf16 *hhi, *hlo, *wqkvh, *wqkvl, *wprojh, *wprojl, *wfc1h, *wfc1l, *wfc2h, *wfc2l;
    bf16 *qhi, *qlo, *khi, *klo, *vThi, *vTlo, *phi, *plo, *atthi, *attlo, *mlphi, *mlplo;
    float *scb, *x1b;
    cudaGetSymbolAddress((void**)&hhi,   g_hhi);   cudaGetSymbolAddress((void**)&hlo,   g_hlo);
    cudaGetSymbolAddress((void**)&wqkvh, g_wqkvT_hi); cudaGetSymbolAddress((void**)&wqkvl, g_wqkvT_lo);
    cudaGetSymbolAddress((void**)&wprojh,g_wprojT_hi);cudaGetSymbolAddress((void**)&wprojl,g_wprojT_lo);
    cudaGetSymbolAddress((void**)&wfc1h, g_wfc1T_hi); cudaGetSymbolAddress((void**)&wfc1l, g_wfc1T_lo);
    cudaGetSymbolAddress((void**)&wfc2h, g_wfc2T_hi); cudaGetSymbolAddress((void**)&wfc2l, g_wfc2T_lo);
    cudaGetSymbolAddress((void**)&qhi,   g_qhi);   cudaGetSymbolAddress((void**)&qlo,   g_qlo);
    cudaGetSymbolAddress((void**)&khi,   g_khi);   cudaGetSymbolAddress((void**)&klo,   g_klo);
    cudaGetSymbolAddress((void**)&vThi,  g_vThi);  cudaGetSymbolAddress((void**)&vTlo,  g_vTlo);
    cudaGetSymbolAddress((void**)&phi,   g_phi);   cudaGetSymbolAddress((void**)&plo,   g_plo);
    cudaGetSymbolAddress((void**)&atthi, g_atthi); cudaGetSymbolAddress((void**)&attlo, g_attlo);
    cudaGetSymbolAddress((void**)&mlphi, g_mlphi); cudaGetSymbolAddress((void**)&mlplo, g_mlplo);
    cudaGetSymbolAddress((void**)&scb,   g_sc);
    cudaGetSymbolAddress((void**)&x1b,   g_x1);

    // weight transpose + hi/lo split
    convT_kernel<<<dim3(3 * EMBED / 32, EMBED / 32), 256>>>(w_qkv,  wqkvh,  wqkvl,  EMBED, 3 * EMBED);
    convT_kernel<<<dim3(EMBED / 32,     EMBED / 32), 256>>>(w_proj, wprojh, wprojl, EMBED, EMBED);
    convT_kernel<<<dim3(MLPH / 32,      EMBED / 32), 256>>>(w_fc1,  wfc1h,  wfc1l,  EMBED, MLPH);
    convT_kernel<<<dim3(EMBED / 32,     MLPH / 32),  256>>>(w_fc2,  wfc2h,  wfc2l,  MLPH,  EMBED);

    // 1. ln1 -> h (hi/lo)
    ln_kernel<<<NTOK, 256>>>(x, g1, be1, hhi, hlo);
    // 2. qkv = h @ w_qkv, scatter q/k (head-major) + vT
    mma_gemm<128, 256, EPI_QKV><<<dim3(3 * EMBED / 128, NTOK / 128, 1), 256>>>(
        hhi, hlo, wqkvh, wqkvl, nullptr, nullptr, nullptr, nullptr, nullptr,
        NTOK, 3 * EMBED, EMBED, 0, 0);
    // 3. scores = Q @ K^T * 0.125
    mma_gemm<128, 256, EPI_SCORES><<<dim3(SEQ / 128, SEQ / 128, BH), 256>>>(
        qhi, qlo, khi, klo, nullptr, nullptr, scb, nullptr, nullptr,
        SEQ, SEQ, HDIM, (size_t)SEQ * HDIM, (size_t)SEQ * HDIM);
    // 4. softmax -> P (hi/lo)
    softmax_kernel<<<BH * SEQ, 256>>>(scb, phi, plo);
    // 5. attn = P @ V  (V stored transposed [Dh][S])
    mma_gemm<64, 128, EPI_PV><<<dim3(1, SEQ / 128, BH), 128>>>(
        phi, plo, vThi, vTlo, nullptr, nullptr, nullptr, nullptr, nullptr,
        SEQ, HDIM, SEQ, (size_t)SEQ * SEQ, (size_t)HDIM * SEQ);
    // 6. x1 = x + attn @ w_proj + b_proj
    mma_gemm<128, 256, EPI_BR><<<dim3(EMBED / 128, NTOK / 128, 1), 256>>>(
        atthi, attlo, wprojh, wprojl, b_proj, x, x1b, nullptr, nullptr,
        NTOK, EMBED, EMBED, 0, 0);
    // 7. ln2 -> h2 (hi/lo)
    ln_kernel<<<NTOK, 256>>>(x1b, g2, be2, hhi, hlo);
    // 8. mlp = gelu(h2 @ w_fc1 + b_fc1) (hi/lo)
    mma_gemm<128, 256, EPI_GELU><<<dim3(MLPH / 128, NTOK / 128, 1), 256>>>(
        hhi, hlo, wfc1h, wfc1l, b_fc1, nullptr, nullptr, mlphi, mlplo,
        NTOK, MLPH, EMBED, 0, 0);
    // 9. out = x1 + mlp @ w_fc2 + b_fc2
    mma_gemm<128, 256, EPI_BR><<<dim3(EMBED / 128, NTOK / 128, 1), 256>>>(
        mlphi, mlplo, wfc2h, wfc2l, b_fc2, x1b, out, nullptr, nullptr,
        NTOK, EMBED, MLPH, 0, 0);
}

// round 3
// speedup vs baseline: 2.2576x; 1.1684x over previous
#include <cuda_runtime.h>
#include <cuda_bf16.h>
#include <math.h>
#include <stdint.h>

#define EMBED 1024
#define NHEAD 16
#define HDIM  64
#define MLPH  4096
#define BATCH 2
#define SEQ   2048
#define NTOK  4096   // BATCH*SEQ
#define BH    32     // BATCH*NHEAD

using bf16 = __nv_bfloat16;

// ---------------- scratch (static device globals; no allocation) ----------------
__device__ __align__(16) bf16 g_hhi [(size_t)NTOK * EMBED];
__device__ __align__(16) bf16 g_hlo [(size_t)NTOK * EMBED];
__device__ __align__(16) bf16 g_wqkvT_hi[(size_t)3 * EMBED * EMBED];
__device__ __align__(16) bf16 g_wqkvT_lo[(size_t)3 * EMBED * EMBED];
__device__ __align__(16) bf16 g_wprojT_hi[(size_t)EMBED * EMBED];
__device__ __align__(16) bf16 g_wprojT_lo[(size_t)EMBED * EMBED];
__device__ __align__(16) bf16 g_wfc1T_hi[(size_t)EMBED * MLPH];
__device__ __align__(16) bf16 g_wfc1T_lo[(size_t)EMBED * MLPH];
__device__ __align__(16) bf16 g_wfc2T_hi[(size_t)MLPH * EMBED];
__device__ __align__(16) bf16 g_wfc2T_lo[(size_t)MLPH * EMBED];
__device__ __align__(16) bf16 g_qhi [(size_t)NTOK * EMBED];   // [BH][S][Dh]
__device__ __align__(16) bf16 g_qlo [(size_t)NTOK * EMBED];
__device__ __align__(16) bf16 g_khi [(size_t)NTOK * EMBED];
__device__ __align__(16) bf16 g_klo [(size_t)NTOK * EMBED];
__device__ __align__(16) bf16 g_vThi[(size_t)NTOK * EMBED];   // [BH][Dh][S]
__device__ __align__(16) bf16 g_vTlo[(size_t)NTOK * EMBED];
__device__ __align__(16) bf16 g_atthi[(size_t)NTOK * EMBED];  // [B*S][D]
__device__ __align__(16) bf16 g_attlo[(size_t)NTOK * EMBED];
__device__ __align__(16) float g_x1 [(size_t)NTOK * EMBED];
__device__ __align__(16) bf16 g_mlphi[(size_t)NTOK * MLPH];
__device__ __align__(16) bf16 g_mlplo[(size_t)NTOK * MLPH];

// ---------------- helpers ----------------
__device__ __forceinline__ float warpSum(float v) {
    #pragma unroll
    for (int o = 16; o; o >>= 1) v += __shfl_xor_sync(0xffffffffu, v, o);
    return v;
}
__device__ __forceinline__ void store_hilo2(bf16* __restrict__ Hi, bf16* __restrict__ Lo,
                                            size_t idx, float a, float b) {
    bf16 h0 = __float2bfloat16(a), h1 = __float2bfloat16(b);
    bf16 l0 = __float2bfloat16(a - __bfloat162float(h0));
    bf16 l1 = __float2bfloat16(b - __bfloat162float(h1));
    *(__nv_bfloat162*)(Hi + idx) = __halves2bfloat162(h0, h1);
    *(__nv_bfloat162*)(Lo + idx) = __halves2bfloat162(l0, l1);
}
__device__ __forceinline__ void store_hilo1(bf16* __restrict__ Hi, bf16* __restrict__ Lo,
                                            size_t idx, float a) {
    bf16 h = __float2bfloat16(a);
    Hi[idx] = h;
    Lo[idx] = __float2bfloat16(a - __bfloat162float(h));
}
__device__ __forceinline__ void pack_hilo(float p0, float p1, uint32_t& hi, uint32_t& lo) {
    bf16 h0 = __float2bfloat16(p0), h1 = __float2bfloat16(p1);
    bf16 l0 = __float2bfloat16(p0 - __bfloat162float(h0));
    bf16 l1 = __float2bfloat16(p1 - __bfloat162float(h1));
    __nv_bfloat162 th = __halves2bfloat162(h0, h1);
    __nv_bfloat162 tl = __halves2bfloat162(l0, l1);
    hi = *(uint32_t*)&th;
    lo = *(uint32_t*)&tl;
}
__device__ __forceinline__ void mma16816(float* d, const uint32_t* a, const uint32_t* b) {
    asm volatile(
        "mma.sync.aligned.m16n8k16.row.col.f32.bf16.bf16.f32 "
        "{%0,%1,%2,%3},{%4,%5,%6,%7},{%8,%9},{%0,%1,%2,%3};\n"
        : "+f"(d[0]), "+f"(d[1]), "+f"(d[2]), "+f"(d[3])
        : "r"(a[0]), "r"(a[1]), "r"(a[2]), "r"(a[3]), "r"(b[0]), "r"(b[1]));
}

// ---------------- weight transpose + hi/lo split: W[K][N] -> T[N][K] ----------------
__global__ __launch_bounds__(256) void convT_kernel(
    const float* __restrict__ W, bf16* __restrict__ Thi, bf16* __restrict__ Tlo,
    int K, int N)
{
    __shared__ float t[32][33];
    int n0 = blockIdx.x * 32, k0 = blockIdx.y * 32;
    int tx = threadIdx.x & 31, ty0 = threadIdx.x >> 5;
    #pragma unroll
    for (int r = ty0; r < 32; r += 8)
        t[r][tx] = W[(size_t)(k0 + r) * N + n0 + tx];
    __syncthreads();
    #pragma unroll
    for (int r = ty0; r < 32; r += 8) {
        float v = t[tx][r];
        size_t idx = (size_t)(n0 + r) * K + k0 + tx;
        bf16 h = __float2bfloat16(v);
        Thi[idx] = h;
        Tlo[idx] = __float2bfloat16(v - __bfloat162float(h));
    }
}

// ---------------- LayerNorm: fp32 in -> bf16 hi/lo out ----------------
__global__ __launch_bounds__(256) void ln_kernel(
    const float* __restrict__ x, const float* __restrict__ g,
    const float* __restrict__ b, bf16* __restrict__ Ohi, bf16* __restrict__ Olo)
{
    size_t row = blockIdx.x;
    int tid = threadIdx.x;
    const float4* xr = reinterpret_cast<const float4*>(x + row * EMBED);
    float4 v = xr[tid];
    float s  = v.x + v.y + v.z + v.w;
    float ss = v.x*v.x + v.y*v.y + v.z*v.z + v.w*v.w;
    __shared__ float rs_[8], rss_[8];
    s = warpSum(s); ss = warpSum(ss);
    int w = tid >> 5, l = tid & 31;
    if (l == 0) { rs_[w] = s; rss_[w] = ss; }
    __syncthreads();
    float tot = 0.f, tot2 = 0.f;
    #pragma unroll
    for (int i = 0; i < 8; i++) { tot += rs_[i]; tot2 += rss_[i]; }
    float mu  = tot * (1.0f / EMBED);
    float var = tot2 * (1.0f / EMBED) - mu * mu;
    float rstd = rsqrtf(var + 1e-5f);
    float4 gg = reinterpret_cast<const float4*>(g)[tid];
    float4 bb = reinterpret_cast<const float4*>(b)[tid];
    float r0 = (v.x - mu) * rstd * gg.x + bb.x;
    float r1 = (v.y - mu) * rstd * gg.y + bb.y;
    float r2 = (v.z - mu) * rstd * gg.z + bb.z;
    float r3 = (v.w - mu) * rstd * gg.w + bb.w;
    size_t base = row * EMBED + (size_t)tid * 4;
    store_hilo2(Ohi, Olo, base,     r0, r1);
    store_hilo2(Ohi, Olo, base + 2, r2, r3);
}

// ---------------- Flash attention: fused QK^T -> online softmax -> PV ----------------
// Q [BH][S][Dh] hi/lo, K [BH][S][Dh] hi/lo, V^T [BH][Dh][S] hi/lo.
// Grid: (S/128, BH). 256 threads = 8 warps x 16 q-rows.
#define FA_PAD 72   // bf16 row stride (64 data + 8 pad)

__global__ __launch_bounds__(256, 1) void flash_kernel(
    const bf16* __restrict__ Qhi, const bf16* __restrict__ Qlo,
    const bf16* __restrict__ Khi, const bf16* __restrict__ Klo,
    const bf16* __restrict__ VThi, const bf16* __restrict__ VTlo,
    bf16* __restrict__ Ohi, bf16* __restrict__ Olo)
{
    __shared__ __align__(16) bf16 sm[4 * 64 * FA_PAD];   // 36 KB, unioned
    bf16* sQh = sm;                 // 128 x FA_PAD (Q staging phase)
    bf16* sQl = sm + 2 * 64 * FA_PAD;
    bf16* sKh = sm;                 // 64 x FA_PAD (main loop phase)
    bf16* sKl = sm + 1 * 64 * FA_PAD;
    bf16* sVh = sm + 2 * 64 * FA_PAD;
    bf16* sVl = sm + 3 * 64 * FA_PAD;

    const int tid = threadIdx.x;
    const int wid = tid >> 5, lane = tid & 31;
    const int g = lane >> 2, c4 = lane & 3;
    const int bh = blockIdx.y;
    const int q0 = blockIdx.x * 128;

    const bf16* pQh = Qhi + (size_t)bh * SEQ * HDIM + (size_t)q0 * HDIM;
    const bf16* pQl = Qlo + (size_t)bh * SEQ * HDIM + (size_t)q0 * HDIM;
    const bf16* pKh = Khi + (size_t)bh * SEQ * HDIM;
    const bf16* pKl = Klo + (size_t)bh * SEQ * HDIM;
    const bf16* pVh = VThi + (size_t)bh * HDIM * SEQ;
    const bf16* pVl = VTlo + (size_t)bh * HDIM * SEQ;

    // ---- stage Q tile, pull fragments to registers ----
    #pragma unroll
    for (int i = 0; i < 4; i++) {
        int idx = tid + i * 256;
        int row = idx >> 3, ch = (idx & 7) << 3;
        *(uint4*)&sQh[row * FA_PAD + ch] = *(const uint4*)(pQh + (size_t)row * HDIM + ch);
        *(uint4*)&sQl[row * FA_PAD + ch] = *(const uint4*)(pQl + (size_t)row * HDIM + ch);
    }
    __syncthreads();
    uint32_t qh[4][4], ql[4][4];
    {
        const int r = wid * 16 + g;
        #pragma unroll
        for (int ks = 0; ks < 4; ks++) {
            int kb = ks * 16 + 2 * c4;
            qh[ks][0] = *(const uint32_t*)&sQh[r * FA_PAD + kb];
            qh[ks][1] = *(const uint32_t*)&sQh[(r + 8) * FA_PAD + kb];
            qh[ks][2] = *(const uint32_t*)&sQh[r * FA_PAD + kb + 8];
            qh[ks][3] = *(const uint32_t*)&sQh[(r + 8) * FA_PAD + kb + 8];
            ql[ks][0] = *(const uint32_t*)&sQl[r * FA_PAD + kb];
            ql[ks][1] = *(const uint32_t*)&sQl[(r + 8) * FA_PAD + kb];
            ql[ks][2] = *(const uint32_t*)&sQl[r * FA_PAD + kb + 8];
            ql[ks][3] = *(const uint32_t*)&sQl[(r + 8) * FA_PAD + kb + 8];
        }
    }
    __syncthreads();

    float oacc[8][4];
    #pragma unroll
    for (int i = 0; i < 8; i++)
        #pragma unroll
        for (int j = 0; j < 4; j++) oacc[i][j] = 0.f;
    float m0r = -1e30f, m1r = -1e30f;
    float l0r = 0.f, l1r = 0.f;

    for (int t = 0; t < SEQ / 64; t++) {
        const int s0 = t * 64;
        // load K tile [64 kv][64 dh] and V^T tile [64 dh][64 kv]
        #pragma unroll
        for (int i = 0; i < 2; i++) {
            int idx = tid + i * 256;
            int row = idx >> 3, ch = (idx & 7) << 3;
            *(uint4*)&sKh[row * FA_PAD + ch] = *(const uint4*)(pKh + (size_t)(s0 + row) * HDIM + ch);
            *(uint4*)&sKl[row * FA_PAD + ch] = *(const uint4*)(pKl + (size_t)(s0 + row) * HDIM + ch);
            *(uint4*)&sVh[row * FA_PAD + ch] = *(const uint4*)(pVh + (size_t)row * SEQ + s0 + ch);
            *(uint4*)&sVl[row * FA_PAD + ch] = *(const uint4*)(pVl + (size_t)row * SEQ + s0 + ch);
        }
        __syncthreads();

        // ---- S = Q K^T (3-pass) ----
        float sacc[8][4];
        #pragma unroll
        for (int i = 0; i < 8; i++)
            #pragma unroll
            for (int j = 0; j < 4; j++) sacc[i][j] = 0.f;
        #pragma unroll
        for (int ks = 0; ks < 4; ks++) {
            int kb = ks * 16 + 2 * c4;
            #pragma unroll
            for (int nf = 0; nf < 8; nf++) {
                uint32_t bhh[2], bll[2];
                int n = nf * 8 + g;
                bhh[0] = *(const uint32_t*)&sKh[n * FA_PAD + kb];
                bhh[1] = *(const uint32_t*)&sKh[n * FA_PAD + kb + 8];
                bll[0] = *(const uint32_t*)&sKl[n * FA_PAD + kb];
                bll[1] = *(const uint32_t*)&sKl[n * FA_PAD + kb + 8];
                mma16816(sacc[nf], qh[ks], bhh);
                mma16816(sacc[nf], qh[ks], bll);
                mma16816(sacc[nf], ql[ks], bhh);
            }
        }

        // ---- online softmax ----
        float mx0 = -1e30f, mx1 = -1e30f;
        #pragma unroll
        for (int nf = 0; nf < 8; nf++) {
            sacc[nf][0] *= 0.125f; sacc[nf][1] *= 0.125f;
            sacc[nf][2] *= 0.125f; sacc[nf][3] *= 0.125f;
            mx0 = fmaxf(mx0, fmaxf(sacc[nf][0], sacc[nf][1]));
            mx1 = fmaxf(mx1, fmaxf(sacc[nf][2], sacc[nf][3]));
        }
        mx0 = fmaxf(mx0, __shfl_xor_sync(0xffffffffu, mx0, 1));
        mx0 = fmaxf(mx0, __shfl_xor_sync(0xffffffffu, mx0, 2));
        mx1 = fmaxf(mx1, __shfl_xor_sync(0xffffffffu, mx1, 1));
        mx1 = fmaxf(mx1, __shfl_xor_sync(0xffffffffu, mx1, 2));
        float mn0 = fmaxf(m0r, mx0), mn1 = fmaxf(m1r, mx1);
        float sc0 = __expf(m0r - mn0), sc1 = __expf(m1r - mn1);
        m0r = mn0; m1r = mn1;
        l0r *= sc0; l1r *= sc1;
        #pragma unroll
        for (int nf = 0; nf < 8; nf++) {
            oacc[nf][0] *= sc0; oacc[nf][1] *= sc0;
            oacc[nf][2] *= sc1; oacc[nf][3] *= sc1;
        }

        // P = exp(S - m), hi/lo packed as PV A-fragments
        uint32_t pah[4][4], pal[4][4];
        #pragma unroll
        for (int nf = 0; nf < 8; nf++) {
            float p0 = __expf(sacc[nf][0] - mn0);
            float p1 = __expf(sacc[nf][1] - mn0);
            float p2 = __expf(sacc[nf][2] - mn1);
            float p3 = __expf(sacc[nf][3] - mn1);
            l0r += p0 + p1; l1r += p2 + p3;
            int as = nf >> 1, half = nf & 1;
            pack_hilo(p0, p1, pah[as][half * 2 + 0], pal[as][half * 2 + 0]);
            pack_hilo(p2, p3, pah[as][half * 2 + 1], pal[as][half * 2 + 1]);
        }

        // ---- O += P V (3-pass) ----
        #pragma unroll
        for (int ks = 0; ks < 4; ks++) {
            int kb = ks * 16 + 2 * c4;
            #pragma unroll
            for (int nf = 0; nf < 8; nf++) {
                uint32_t bhh[2], bll[2];
                int n = nf * 8 + g;
                bhh[0] = *(const uint32_t*)&sVh[n * FA_PAD + kb];
                bhh[1] = *(const uint32_t*)&sVh[n * FA_PAD + kb + 8];
                bll[0] = *(const uint32_t*)&sVl[n * FA_PAD + kb];
                bll[1] = *(const uint32_t*)&sVl[n * FA_PAD + kb + 8];
                mma16816(oacc[nf], pah[ks], bhh);
                mma16816(oacc[nf], pah[ks], bll);
                mma16816(oacc[nf], pal[ks], bhh);
            }
        }
        __syncthreads();
    }

    // ---- finalize: divide by l, scatter to [B*S][D] hi/lo ----
    l0r += __shfl_xor_sync(0xffffffffu, l0r, 1);
    l0r += __shfl_xor_sync(0xffffffffu, l0r, 2);
    l1r += __shfl_xor_sync(0xffffffffu, l1r, 1);
    l1r += __shfl_xor_sync(0xffffffffu, l1r, 2);
    float inv0 = 1.0f / l0r, inv1 = 1.0f / l1r;
    const int bb = bh >> 4, hd = bh & 15;
    const int r = q0 + wid * 16 + g;
    #pragma unroll
    for (int nf = 0; nf < 8; nf++) {
        int col = hd * HDIM + nf * 8 + 2 * c4;
        size_t i0 = ((size_t)(bb * SEQ + r)) * EMBED + col;
        size_t i1 = ((size_t)(bb * SEQ + r + 8)) * EMBED + col;
        store_hilo2(Ohi, Olo, i0, oacc[nf][0] * inv0, oacc[nf][1] * inv0);
        store_hilo2(Ohi, Olo, i1, oacc[nf][2] * inv1, oacc[nf][3] * inv1);
    }
}

// ---------------- 3-pass split-bf16 tensor-core GEMM (dense layers) ----------------
enum { EPI_QKV = 0, EPI_BR = 3, EPI_GELU = 4 };

template<int EPI>
__global__ __launch_bounds__(256) void mma_gemm(
    const bf16* __restrict__ Ahi, const bf16* __restrict__ Alo,
    const bf16* __restrict__ Bhi, const bf16* __restrict__ Blo,
    const float* __restrict__ bias, const float* __restrict__ res,
    float* __restrict__ Cf, bf16* __restrict__ Chi, bf16* __restrict__ Clo,
    int M, int N, int K)
{
    constexpr int BM = 128, BN = 128, BK = 32, NT = 256;
    constexpr int WN = BN / 32;
    constexpr int A_IT = (BM * 4) / NT;
    constexpr int B_IT = (BN * 4) / NT;
    constexpr int LDS_ = 40;

    __shared__ __align__(16) bf16 Ash[BM * LDS_];
    __shared__ __align__(16) bf16 Asl[BM * LDS_];
    __shared__ __align__(16) bf16 Bsh[BN * LDS_];
    __shared__ __align__(16) bf16 Bsl[BN * LDS_];

    const int tid = threadIdx.x;
    const int wid = tid >> 5, lane = tid & 31;
    const int g = lane >> 2, c4 = lane & 3;
    const int wm = wid / WN, wn = wid % WN;
    const int m0 = blockIdx.y * BM, n0 = blockIdx.x * BN;

    float acc[4][4][4];
    #pragma unroll
    for (int i = 0; i < 4; i++)
        #pragma unroll
        for (int j = 0; j < 4; j++)
            #pragma unroll
            for (int k = 0; k < 4; k++) acc[i][j][k] = 0.f;

    uint4 rAh[A_IT], rAl[A_IT], rBh[B_IT], rBl[B_IT];

    #pragma unroll
    for (int i = 0; i < A_IT; i++) {
        int idx = tid + i * NT; int row = idx >> 2; int ch = (idx & 3) << 3;
        size_t off = (size_t)(m0 + row) * K + ch;
        rAh[i] = *(const uint4*)(Ahi + off);
        rAl[i] = *(const uint4*)(Alo + off);
    }
    #pragma unroll
    for (int i = 0; i < B_IT; i++) {
        int idx = tid + i * NT; int row = idx >> 2; int ch = (idx & 3) << 3;
        size_t off = (size_t)(n0 + row) * K + ch;
        rBh[i] = *(const uint4*)(Bhi + off);
        rBl[i] = *(const uint4*)(Blo + off);
    }

    for (int kt = 0; kt < K; kt += BK) {
        #pragma unroll
        for (int i = 0; i < A_IT; i++) {
            int idx = tid + i * NT; int row = idx >> 2; int ch = (idx & 3) << 3;
            *(uint4*)&Ash[row * LDS_ + ch] = rAh[i];
            *(uint4*)&Asl[row * LDS_ + ch] = rAl[i];
        }
        #pragma unroll
        for (int i = 0; i < B_IT; i++) {
            int idx = tid + i * NT; int row = idx >> 2; int ch = (idx & 3) << 3;
            *(uint4*)&Bsh[row * LDS_ + ch] = rBh[i];
            *(uint4*)&Bsl[row * LDS_ + ch] = rBl[i];
        }
        __syncthreads();

        if (kt + BK < K) {
            #pragma unroll
            for (int i = 0; i < A_IT; i++) {
                int idx = tid + i * NT; int row = idx >> 2; int ch = (idx & 3) << 3;
                size_t off = (size_t)(m0 + row) * K + kt + BK + ch;
                rAh[i] = *(const uint4*)(Ahi + off);
                rAl[i] = *(const uint4*)(Alo + off);
            }
            #pragma unroll
            for (int i = 0; i < B_IT; i++) {
                int idx = tid + i * NT; int row = idx >> 2; int ch = (idx & 3) << 3;
                size_t off = (size_t)(n0 + row) * K + kt + BK + ch;
                rBh[i] = *(const uint4*)(Bhi + off);
                rBl[i] = *(const uint4*)(Blo + off);
            }
        }

        #pragma unroll
        for (int ks = 0; ks < 2; ks++) {
            const int kb = ks * 16 + 2 * c4;
            uint32_t ah[4][4], al[4][4], bh[4][2], bl[4][2];
            #pragma unroll
            for (int mf = 0; mf < 4; mf++) {
                int r = wm * 64 + mf * 16 + g;
                ah[mf][0] = *(const uint32_t*)&Ash[r * LDS_ + kb];
                ah[mf][1] = *(const uint32_t*)&Ash[(r + 8) * LDS_ + kb];
                ah[mf][2] = *(const uint32_t*)&Ash[r * LDS_ + kb + 8];
                ah[mf][3] = *(const uint32_t*)&Ash[(r + 8) * LDS_ + kb + 8];
                al[mf][0] = *(const uint32_t*)&Asl[r * LDS_ + kb];
                al[mf][1] = *(const uint32_t*)&Asl[(r + 8) * LDS_ + kb];
                al[mf][2] = *(const uint32_t*)&Asl[r * LDS_ + kb + 8];
                al[mf][3] = *(const uint32_t*)&Asl[(r + 8) * LDS_ + kb + 8];
            }
            #pragma unroll
            for (int nf = 0; nf < 4; nf++) {
                int nn = wn * 32 + nf * 8 + g;
                bh[nf][0] = *(const uint32_t*)&Bsh[nn * LDS_ + kb];
                bh[nf][1] = *(const uint32_t*)&Bsh[nn * LDS_ + kb + 8];
                bl[nf][0] = *(const uint32_t*)&Bsl[nn * LDS_ + kb];
                bl[nf][1] = *(const uint32_t*)&Bsl[nn * LDS_ + kb + 8];
            }
            #pragma unroll
            for (int mf = 0; mf < 4; mf++)
                #pragma unroll
                for (int nf = 0; nf < 4; nf++) {
                    mma16816(acc[mf][nf], ah[mf], bh[nf]);
                    mma16816(acc[mf][nf], ah[mf], bl[nf]);
                    mma16816(acc[mf][nf], al[mf], bh[nf]);
                }
        }
        __syncthreads();
    }

    // ---------------- epilogue ----------------
    #pragma unroll
    for (int mf = 0; mf < 4; mf++) {
        int r0 = m0 + wm * 64 + mf * 16 + g;
        #pragma unroll
        for (int nf = 0; nf < 4; nf++) {
            int cc = n0 + wn * 32 + nf * 8 + 2 * c4;
            float d0 = acc[mf][nf][0], d1 = acc[mf][nf][1];
            float d2 = acc[mf][nf][2], d3 = acc[mf][nf][3];

            if constexpr (EPI == EPI_BR) {
                float b0 = bias[cc], b1 = bias[cc + 1];
                size_t i0 = (size_t)r0 * N + cc, i1 = (size_t)(r0 + 8) * N + cc;
                *(float2*)&Cf[i0] = make_float2(d0 + b0 + res[i0], d1 + b1 + res[i0 + 1]);
                *(float2*)&Cf[i1] = make_float2(d2 + b0 + res[i1], d3 + b1 + res[i1 + 1]);
            } else if constexpr (EPI == EPI_GELU) {
                float b0 = bias[cc], b1 = bias[cc + 1];
                float v0 = d0 + b0, v1 = d1 + b1, v2 = d2 + b0, v3 = d3 + b1;
                v0 = 0.5f * v0 * (1.0f + erff(v0 * 0.70710678118654752f));
                v1 = 0.5f * v1 * (1.0f + erff(v1 * 0.70710678118654752f));
                v2 = 0.5f * v2 * (1.0f + erff(v2 * 0.70710678118654752f));
                v3 = 0.5f * v3 * (1.0f + erff(v3 * 0.70710678118654752f));
                store_hilo2(Chi, Clo, (size_t)r0 * N + cc, v0, v1);
                store_hilo2(Chi, Clo, (size_t)(r0 + 8) * N + cc, v2, v3);
            } else { // EPI_QKV
                int part = cc >> 10, rem = cc & 1023, hd = rem >> 6, dd = rem & 63;
                #pragma unroll
                for (int rr = 0; rr < 2; rr++) {
                    int r = r0 + rr * 8;
                    float e0 = rr ? d2 : d0, e1 = rr ? d3 : d1;
                    int bb = r >> 11, s = r & 2047;
                    size_t bh_ = (size_t)(bb * NHEAD + hd);
                    if (part == 0) {
                        store_hilo2(g_qhi, g_qlo, (bh_ * SEQ + s) * HDIM + dd, e0, e1);
                    } else if (part == 1) {
                        store_hilo2(g_khi, g_klo, (bh_ * SEQ + s) * HDIM + dd, e0, e1);
                    } else {
                        size_t vb = (bh_ * HDIM + dd) * SEQ + s;
                        store_hilo1(g_vThi, g_vTlo, vb, e0);
                        store_hilo1(g_vThi, g_vTlo, vb + SEQ, e1);
                    }
                }
            }
        }
    }
}

// ---------------- host launcher ----------------
extern "C" void kernel_launch(void* const* d_in, const int* in_sizes, int n_in,
                              void* d_out, int out_size)
{
    const float* x      = (const float*)d_in[0];
    const float* w_qkv  = (const float*)d_in[1];
    const float* w_proj = (const float*)d_in[2];
    const float* b_proj = (const float*)d_in[3];
    const float* w_fc1  = (const float*)d_in[4];
    const float* b_fc1  = (const float*)d_in[5];
    const float* w_fc2  = (const float*)d_in[6];
    const float* b_fc2  = (const float*)d_in[7];
    const float* g1     = (const float*)d_in[8];
    const float* be1    = (const float*)d_in[9];
    const float* g2     = (const float*)d_in[10];
    const float* be2    = (const float*)d_in[11];
    float* out = (float*)d_out;

    bf16 *hhi, *hlo, *wqkvh, *wqkvl, *wprojh, *wprojl, *wfc1h, *wfc1l, *wfc2h, *wfc2l;
    bf16 *qhi, *qlo, *khi, *klo, *vThi, *vTlo, *atthi, *attlo, *mlphi, *mlplo;
    float *x1b;
    cudaGetSymbolAddress((void**)&hhi,   g_hhi);   cudaGetSymbolAddress((void**)&hlo,   g_hlo);
    cudaGetSymbolAddress((void**)&wqkvh, g_wqkvT_hi); cudaGetSymbolAddress((void**)&wqkvl, g_wqkvT_lo);
    cudaGetSymbolAddress((void**)&wprojh,g_wprojT_hi);cudaGetSymbolAddress((void**)&wprojl,g_wprojT_lo);
    cudaGetSymbolAddress((void**)&wfc1h, g_wfc1T_hi); cudaGetSymbolAddress((void**)&wfc1l, g_wfc1T_lo);
    cudaGetSymbolAddress((void**)&wfc2h, g_wfc2T_hi); cudaGetSymbolAddress((void**)&wfc2l, g_wfc2T_lo);
    cudaGetSymbolAddress((void**)&qhi,   g_qhi);   cudaGetSymbolAddress((void**)&qlo,   g_qlo);
    cudaGetSymbolAddress((void**)&khi,   g_khi);   cudaGetSymbolAddress((void**)&klo,   g_klo);
    cudaGetSymbolAddress((void**)&vThi,  g_vThi);  cudaGetSymbolAddress((void**)&vTlo,  g_vTlo);
    cudaGetSymbolAddress((void**)&atthi, g_atthi); cudaGetSymbolAddress((void**)&attlo, g_attlo);
    cudaGetSymbolAddress((void**)&mlphi, g_mlphi); cudaGetSymbolAddress((void**)&mlplo, g_mlplo);
    cudaGetSymbolAddress((void**)&x1b,   g_x1);

    // weight transpose + hi/lo split
    convT_kernel<<<dim3(3 * EMBED / 32, EMBED / 32), 256>>>(w_qkv,  wqkvh,  wqkvl,  EMBED, 3 * EMBED);
    convT_kernel<<<dim3(EMBED / 32,     EMBED / 32), 256>>>(w_proj, wprojh, wprojl, EMBED, EMBED);
    convT_kernel<<<dim3(MLPH / 32,      EMBED / 32), 256>>>(w_fc1,  wfc1h,  wfc1l,  EMBED, MLPH);
    convT_kernel<<<dim3(EMBED / 32,     MLPH / 32),  256>>>(w_fc2,  wfc2h,  wfc2l,  MLPH,  EMBED);

    // 1. ln1 -> h (hi/lo)
    ln_kernel<<<NTOK, 256>>>(x, g1, be1, hhi, hlo);
    // 2. qkv = h @ w_qkv, scatter q/k (head-major) + vT
    mma_gemm<EPI_QKV><<<dim3(3 * EMBED / 128, NTOK / 128), 256>>>(
        hhi, hlo, wqkvh, wqkvl, nullptr, nullptr, nullptr, nullptr, nullptr,
        NTOK, 3 * EMBED, EMBED);
    // 3. fused flash attention -> att (hi/lo, [B*S][D])
    flash_kernel<<<dim3(SEQ / 128, BH), 256>>>(
        qhi, qlo, khi, klo, vThi, vTlo, atthi, attlo);
    // 4. x1 = x + att @ w_proj + b_proj
    mma_gemm<EPI_BR><<<dim3(EMBED / 128, NTOK / 128), 256>>>(
        atthi, attlo, wprojh, wprojl, b_proj, x, x1b, nullptr, nullptr,
        NTOK, EMBED, EMBED);
    // 5. ln2 -> h2 (hi/lo)
    ln_kernel<<<NTOK, 256>>>(x1b, g2, be2, hhi, hlo);
    // 6. mlp = gelu(h2 @ w_fc1 + b_fc1) (hi/lo)
    mma_gemm<EPI_GELU><<<dim3(MLPH / 128, NTOK / 128), 256>>>(
        hhi, hlo, wfc1h, wfc1l, b_fc1, nullptr, nullptr, mlphi, mlplo,
        NTOK, MLPH, EMBED);
    // 7. out = x1 + mlp @ w_fc2 + b_fc2
    mma_gemm<EPI_BR><<<dim3(EMBED / 128, NTOK / 128), 256>>>(
        mlphi, mlplo, wfc2h, wfc2l, b_fc2, x1b, out, nullptr, nullptr,
        NTOK, EMBED, MLPH);
}